// round 2
// baseline (speedup 1.0000x reference)
#include <cuda_runtime.h>
#include <math.h>

#define SC 64
#define VC 32
#define DIMF 160
#define NB 64
#define TBL 4096
#define CUTOFF_F 5.0f

// Scratch (static device globals — no allocation)
__device__ float g_table[TBL];
__device__ double g_ewsum;

__global__ void k_zero_ew() { g_ewsum = 0.0; }

// Tabulate t(d) = sigmoid( cut(d) * sum_b exp(-0.5*((d-c_b)/w_b)^2) * pw_b + pb )
__global__ void k_build_table(const float* __restrict__ centers,
                              const float* __restrict__ widths,
                              const float* __restrict__ pw,
                              const float* __restrict__ pb) {
    int i = blockIdx.x * blockDim.x + threadIdx.x;
    if (i >= TBL) return;
    float d = CUTOFF_F * (float)i / (float)(TBL - 1);
    float acc = 0.f;
#pragma unroll 8
    for (int b = 0; b < NB; b++) {
        float z = (d - centers[b]) / widths[b];
        acc += expf(-0.5f * z * z) * pw[b];
    }
    float cut = 0.5f * (cosf(3.14159265358979323846f * d / CUTOFF_F) + 1.0f);
    float t = acc * cut + pb[0];
    g_table[i] = 1.0f / (1.0f + expf(-t));
}

// Per-edge: distance -> table lerp -> block-reduced sum into g_ewsum
__global__ void k_edge_w(const int* __restrict__ ei,
                         const float* __restrict__ pos, int E) {
    int e = blockIdx.x * blockDim.x + threadIdx.x;
    float v = 0.f;
    if (e < E) {
        int s = ei[e];
        int d = ei[E + e];
        float dx = pos[3*s+0] - pos[3*d+0];
        float dy = pos[3*s+1] - pos[3*d+1];
        float dz = pos[3*s+2] - pos[3*d+2];
        float dist = sqrtf(dx*dx + dy*dy + dz*dz);
        float u = fminf(dist, CUTOFF_F) * ((float)(TBL - 1) / CUTOFF_F);
        int i0 = (int)u;
        if (i0 > TBL - 2) i0 = TBL - 2;
        float f = u - (float)i0;
        float t0 = g_table[i0];
        float t1 = g_table[i0 + 1];
        v = t0 + f * (t1 - t0);
    }
#pragma unroll
    for (int o = 16; o > 0; o >>= 1) v += __shfl_down_sync(0xffffffffu, v, o);
    __shared__ float ws[8];
    int lane = threadIdx.x & 31, w = threadIdx.x >> 5;
    if (lane == 0) ws[w] = v;
    __syncthreads();
    if (threadIdx.x < 8) {
        v = ws[threadIdx.x];
#pragma unroll
        for (int o = 4; o > 0; o >>= 1) v += __shfl_down_sync(0xffu, v, o);
        if (threadIdx.x == 0) atomicAdd(&g_ewsum, (double)v);
    }
}

// Scatter-add raw x[src] rows (160 f32 = 40 float4) into out[dst].
// Block handles 32 edges; indices staged in shared to avoid 40x redundant loads.
__global__ void k_scatter(const int* __restrict__ ei,
                          const float* __restrict__ x,
                          float* __restrict__ out, int E) {
    __shared__ int ss[32], sd[32];
    int base = blockIdx.x * 32;
    int t = threadIdx.x;
    if (t < 32) {
        int e = base + t;
        ss[t] = (e < E) ? ei[e] : 0;
    } else if (t < 64) {
        int e = base + t - 32;
        sd[t - 32] = (e < E) ? ei[E + e] : 0;
    }
    __syncthreads();
#pragma unroll
    for (int it = 0; it < 5; it++) {
        int j = t + it * 256;          // 0..1279 = 32 edges * 40 float4
        int el = j / 40;
        int k = j - el * 40;
        if (base + el >= E) continue;  // no sync inside loop: safe
        float4 v = *reinterpret_cast<const float4*>(x + (size_t)ss[el] * DIMF + k * 4);
        float* dp = out + (size_t)sd[el] * DIMF + k * 4;
        asm volatile("red.global.add.v4.f32 [%0], {%1, %2, %3, %4};"
                     :: "l"(dp), "f"(v.x), "f"(v.y), "f"(v.z), "f"(v.w)
                     : "memory");
    }
}

// Per-node finalize: scalar path a0 @ W0 /8, vector path (per-component) @ W1 /sqrt(32),
// scale by edge_w, LayerNorm+SiLU on first 64 channels. In-place on out.
__global__ void k_finalize(float* __restrict__ out,
                           const float* __restrict__ W0,
                           const float* __restrict__ W1,
                           const float* __restrict__ gamma,
                           const float* __restrict__ beta,
                           int E) {
    __shared__ float a[DIMF];
    __shared__ float s[SC];
    int n = blockIdx.x;
    int t = threadIdx.x;
    a[t] = out[(size_t)n * DIMF + t];
    __syncthreads();
    float ew = (float)(g_ewsum / (double)E);
    float r;
    if (t < SC) {
        float acc = 0.f;
#pragma unroll
        for (int i = 0; i < SC; i++) acc += a[i] * W0[i * SC + t];
        r = acc * ew * 0.125f;              // 1/sqrt(64)
        s[t] = r;
    } else {
        int k = t - SC;
        int dch = k / 3;
        int j = k - dch * 3;
        float acc = 0.f;
#pragma unroll
        for (int c = 0; c < VC; c++) acc += a[SC + 3 * c + j] * W1[c * VC + dch];
        r = acc * ew * 0.17677669529663689f; // 1/sqrt(32)
    }
    __syncthreads();
    if (t < SC) {
        float mu = 0.f, m2 = 0.f;
#pragma unroll
        for (int i = 0; i < SC; i++) { float si = s[i]; mu += si; m2 += si * si; }
        mu *= (1.0f / SC);
        float var = m2 * (1.0f / SC) - mu * mu;
        float xln = (r - mu) * rsqrtf(var + 1e-5f) * gamma[t] + beta[t];
        r = xln / (1.0f + expf(-xln));       // SiLU
    }
    out[(size_t)n * DIMF + t] = r;
}

extern "C" void kernel_launch(void* const* d_in, const int* in_sizes, int n_in,
                              void* d_out, int out_size) {
    const float* x       = (const float*)d_in[0];
    const float* pos     = (const float*)d_in[1];
    const int*   ei      = (const int*)d_in[2];   // int32: JAX x64 disabled
    // d_in[3] = edge_rand: unused (rotation cancels algebraically)
    const float* W0      = (const float*)d_in[4];
    const float* W1      = (const float*)d_in[5];
    const float* centers = (const float*)d_in[6];
    const float* widths  = (const float*)d_in[7];
    const float* pw      = (const float*)d_in[8];
    const float* pb      = (const float*)d_in[9];
    const float* gamma   = (const float*)d_in[10];
    const float* beta    = (const float*)d_in[11];
    float* out = (float*)d_out;

    int N = in_sizes[0] / DIMF;
    int E = in_sizes[2] / 2;

    cudaMemsetAsync(out, 0, (size_t)N * DIMF * sizeof(float), 0);
    k_zero_ew<<<1, 1>>>();
    k_build_table<<<(TBL + 255) / 256, 256>>>(centers, widths, pw, pb);
    k_edge_w<<<(E + 255) / 256, 256>>>(ei, pos, E);
    k_scatter<<<(E + 31) / 32, 256>>>(ei, x, out, E);
    k_finalize<<<N, DIMF>>>(out, W0, W1, gamma, beta, E);
}

// round 3
// speedup vs baseline: 1.1931x; 1.1931x over previous
#include <cuda_runtime.h>
#include <math.h>

#define SC 64
#define VC 32
#define DIMF 160
#define NB 64
#define TBL 4096
#define CUTOFF_F 5.0f

__device__ float g_table[TBL];
__device__ double g_ewsum;

// Tabulate t(d) = sigmoid( cut(d) * sum_b exp(-0.5*((d-c_b)/w_b)^2) * pw_b + pb )
// Thread 0 also zeroes the edge-weight accumulator (ordered before k_edge_w by launch order).
__global__ void k_build_table(const float* __restrict__ centers,
                              const float* __restrict__ widths,
                              const float* __restrict__ pw,
                              const float* __restrict__ pb) {
    int i = blockIdx.x * blockDim.x + threadIdx.x;
    if (i == 0) g_ewsum = 0.0;
    if (i >= TBL) return;
    float d = CUTOFF_F * (float)i / (float)(TBL - 1);
    float acc = 0.f;
#pragma unroll 8
    for (int b = 0; b < NB; b++) {
        float z = (d - centers[b]) / widths[b];
        acc += expf(-0.5f * z * z) * pw[b];
    }
    float cut = 0.5f * (cosf(3.14159265358979323846f * d / CUTOFF_F) + 1.0f);
    float t = acc * cut + pb[0];
    g_table[i] = 1.0f / (1.0f + expf(-t));
}

// Per-edge: distance -> table lerp -> block-reduced sum into g_ewsum
__global__ void k_edge_w(const int* __restrict__ ei,
                         const float* __restrict__ pos, int E) {
    int e = blockIdx.x * blockDim.x + threadIdx.x;
    float v = 0.f;
    if (e < E) {
        int s = ei[e];
        int d = ei[E + e];
        float dx = pos[3*s+0] - pos[3*d+0];
        float dy = pos[3*s+1] - pos[3*d+1];
        float dz = pos[3*s+2] - pos[3*d+2];
        float dist = sqrtf(dx*dx + dy*dy + dz*dz);
        float u = fminf(dist, CUTOFF_F) * ((float)(TBL - 1) / CUTOFF_F);
        int i0 = (int)u;
        if (i0 > TBL - 2) i0 = TBL - 2;
        float f = u - (float)i0;
        float t0 = g_table[i0];
        float t1 = g_table[i0 + 1];
        v = t0 + f * (t1 - t0);
    }
#pragma unroll
    for (int o = 16; o > 0; o >>= 1) v += __shfl_down_sync(0xffffffffu, v, o);
    __shared__ float ws[8];
    int lane = threadIdx.x & 31, w = threadIdx.x >> 5;
    if (lane == 0) ws[w] = v;
    __syncthreads();
    if (threadIdx.x < 8) {
        v = ws[threadIdx.x];
#pragma unroll
        for (int o = 4; o > 0; o >>= 1) v += __shfl_down_sync(0xffu, v, o);
        if (threadIdx.x == 0) atomicAdd(&g_ewsum, (double)v);
    }
}

// Scatter-add raw x[src] rows (160 f32 = 40 float4) into out[dst].
// ~LTS-roofline-bound (512 MB through L2 at ~6300 B/cyc) — leave alone.
__global__ void k_scatter(const int* __restrict__ ei,
                          const float* __restrict__ x,
                          float* __restrict__ out, int E) {
    __shared__ int ss[32], sd[32];
    int base = blockIdx.x * 32;
    int t = threadIdx.x;
    if (t < 32) {
        int e = base + t;
        ss[t] = (e < E) ? ei[e] : 0;
    } else if (t < 64) {
        int e = base + t - 32;
        sd[t - 32] = (e < E) ? ei[E + e] : 0;
    }
    __syncthreads();
#pragma unroll
    for (int it = 0; it < 5; it++) {
        int j = t + it * 256;          // 0..1279 = 32 edges * 40 float4
        int el = j / 40;
        int k = j - el * 40;
        if (base + el >= E) continue;
        float4 v = *reinterpret_cast<const float4*>(x + (size_t)ss[el] * DIMF + k * 4);
        float* dp = out + (size_t)sd[el] * DIMF + k * 4;
        asm volatile("red.global.add.v4.f32 [%0], {%1, %2, %3, %4};"
                     :: "l"(dp), "f"(v.x), "f"(v.y), "f"(v.z), "f"(v.w)
                     : "memory");
    }
}

// Persistent finalize: W columns register-resident (loaded once per block),
// activations broadcast from shared via LDS.128, grid-stride over nodes.
// Thread t<64: scalar output t (needs W0[:,t], 64 regs).
// Thread t>=64: vector output (dch=(t-64)/3, j=(t-64)%3) (needs W1[:,dch], 32 regs).
__global__ void __launch_bounds__(DIMF) k_finalize(
        float* __restrict__ out,
        const float* __restrict__ W0,
        const float* __restrict__ W1,
        const float* __restrict__ gamma,
        const float* __restrict__ beta,
        int N, int E) {
    __shared__ float4 sa4[SC / 4];       // scalar inputs, float4 view
    __shared__ float4 sv4[3 * VC / 4];   // vector inputs transposed: sv[j][c]
    __shared__ float red[4];

    int t = threadIdx.x;
    float Wreg[SC];
    int dch = 0, jj = 0;
    float gam = 0.f, bet = 0.f;

    if (t < SC) {
#pragma unroll
        for (int i = 0; i < SC; i++) Wreg[i] = W0[i * SC + t];
        gam = gamma[t];
        bet = beta[t];
    } else {
        int k = t - SC;
        dch = k / 3;
        jj = k - dch * 3;
#pragma unroll
        for (int c = 0; c < VC; c++) Wreg[c] = W1[c * VC + dch];
    }
    float ew = (float)(g_ewsum / (double)E);
    float ews = ew * 0.125f;                  // 1/sqrt(64)
    float ewv = ew * 0.17677669529663689f;    // 1/sqrt(32)

    float* sa = reinterpret_cast<float*>(sa4);
    float* sv = reinterpret_cast<float*>(sv4);

    for (int n = blockIdx.x; n < N; n += gridDim.x) {
        float v = out[(size_t)n * DIMF + t];
        if (t < SC) sa[t] = v;
        else {
            int k = t - SC;
            int c = k / 3, j = k - c * 3;
            sv[j * VC + c] = v;
        }
        __syncthreads();

        float acc = 0.f;
        if (t < SC) {
#pragma unroll
            for (int i = 0; i < SC / 4; i++) {
                float4 a4 = sa4[i];
                acc = fmaf(a4.x, Wreg[4*i+0], acc);
                acc = fmaf(a4.y, Wreg[4*i+1], acc);
                acc = fmaf(a4.z, Wreg[4*i+2], acc);
                acc = fmaf(a4.w, Wreg[4*i+3], acc);
            }
            acc *= ews;
            // LN statistics over the 64 scalar outputs (2 warps)
            float s1 = acc, s2 = acc * acc;
#pragma unroll
            for (int o = 16; o > 0; o >>= 1) {
                s1 += __shfl_xor_sync(0xffffffffu, s1, o);
                s2 += __shfl_xor_sync(0xffffffffu, s2, o);
            }
            if ((t & 31) == 0) {
                red[(t >> 5) * 2 + 0] = s1;
                red[(t >> 5) * 2 + 1] = s2;
            }
        } else {
            const float4* svr = &sv4[jj * (VC / 4)];
#pragma unroll
            for (int c = 0; c < VC / 4; c++) {
                float4 a4 = svr[c];
                acc = fmaf(a4.x, Wreg[4*c+0], acc);
                acc = fmaf(a4.y, Wreg[4*c+1], acc);
                acc = fmaf(a4.z, Wreg[4*c+2], acc);
                acc = fmaf(a4.w, Wreg[4*c+3], acc);
            }
            acc *= ewv;
        }
        __syncthreads();

        float res = acc;
        if (t < SC) {
            float mu  = (red[0] + red[2]) * (1.0f / SC);
            float var = (red[1] + red[3]) * (1.0f / SC) - mu * mu;
            float xln = (acc - mu) * rsqrtf(var + 1e-5f) * gam + bet;
            res = xln / (1.0f + expf(-xln));
        }
        out[(size_t)n * DIMF + t] = res;
        __syncthreads();   // protect red[]/sa/sv against next iteration
    }
}

extern "C" void kernel_launch(void* const* d_in, const int* in_sizes, int n_in,
                              void* d_out, int out_size) {
    const float* x       = (const float*)d_in[0];
    const float* pos     = (const float*)d_in[1];
    const int*   ei      = (const int*)d_in[2];   // int32 (JAX x64 disabled)
    // d_in[3] = edge_rand: unused (rotation cancels algebraically)
    const float* W0      = (const float*)d_in[4];
    const float* W1      = (const float*)d_in[5];
    const float* centers = (const float*)d_in[6];
    const float* widths  = (const float*)d_in[7];
    const float* pw      = (const float*)d_in[8];
    const float* pb      = (const float*)d_in[9];
    const float* gamma   = (const float*)d_in[10];
    const float* beta    = (const float*)d_in[11];
    float* out = (float*)d_out;

    int N = in_sizes[0] / DIMF;
    int E = in_sizes[2] / 2;

    cudaMemsetAsync(out, 0, (size_t)N * DIMF * sizeof(float), 0);
    k_build_table<<<(TBL + 255) / 256, 256>>>(centers, widths, pw, pb);
    k_edge_w<<<(E + 255) / 256, 256>>>(ei, pos, E);
    k_scatter<<<(E + 31) / 32, 256>>>(ei, x, out, E);
    k_finalize<<<2368, DIMF>>>(out, W0, W1, gamma, beta, N, E);
}